// round 6
// baseline (speedup 1.0000x reference)
#include <cuda_runtime.h>

#define NN 200000
#define EE 3200000
#define HH 16
#define CC 4
#define GG 256
#define NB ((NN + 1023) / 1024)   // scan blocks = 196

// Scratch (allocation-free __device__ globals); 16B alignment for float4 paths.
__device__ int   g_cnt[NN];            // in-degree histogram
__device__ int   g_rowptr[NN + 1];     // CSR row pointers (by dst)
__device__ int   g_cur[NN];            // fill cursors
__device__ int   g_bsum[NB];           // scan block sums
__device__ float g_dinv[NN];           // rsqrt(deg+1)
__device__ int   g_csr_src[EE];        // src node per CSR slot
__device__ __align__(16) float g_csr_norm[EE];  // per-edge symmetric norm
__device__ __align__(16) float g_t[NN * HH];    // transformed features (gather source)
__device__ __align__(16) float g_acc[NN * HH];  // aggregation output

__global__ void zero_kernel() {
    int n = blockIdx.x * blockDim.x + threadIdx.x;
    if (n < NN) g_cnt[n] = 0;
}

// histogram of dst (edge_index arrives as int32: harness converts int64->int32)
__global__ void hist_kernel(const int* __restrict__ ei) {
    int e = blockIdx.x * blockDim.x + threadIdx.x;
    if (e < EE) atomicAdd(&g_cnt[ei[EE + e]], 1);
}

__global__ void dinv_kernel() {
    int n = blockIdx.x * blockDim.x + threadIdx.x;
    if (n < NN) g_dinv[n] = rsqrtf((float)g_cnt[n] + 1.0f);
}

// ---- 3-kernel exclusive scan of g_cnt -> g_rowptr ----
__device__ __forceinline__ int block_inclusive_scan(int v) {
    __shared__ int ws[32];
    int lane = threadIdx.x & 31, wid = threadIdx.x >> 5;
    int x = v;
#pragma unroll
    for (int o = 1; o < 32; o <<= 1) {
        int y = __shfl_up_sync(0xffffffffu, x, o);
        if (lane >= o) x += y;
    }
    if (lane == 31) ws[wid] = x;
    __syncthreads();
    if (wid == 0) {
        int nw = blockDim.x >> 5;
        int w = (lane < nw) ? ws[lane] : 0;
#pragma unroll
        for (int o = 1; o < 32; o <<= 1) {
            int y = __shfl_up_sync(0xffffffffu, w, o);
            if (lane >= o) w += y;
        }
        ws[lane] = w;
    }
    __syncthreads();
    int base = (wid > 0) ? ws[wid - 1] : 0;
    return x + base;   // inclusive scan across the block
}

__global__ void scan1_kernel() {   // per-block exclusive scan + block totals
    int i = blockIdx.x * 1024 + threadIdx.x;
    int v = (i < NN) ? g_cnt[i] : 0;
    int incl = block_inclusive_scan(v);
    if (i < NN) g_rowptr[i] = incl - v;
    if (threadIdx.x == 1023) g_bsum[blockIdx.x] = incl;
}

__global__ void scan2_kernel() {   // exclusive scan of block totals (single block)
    int i = threadIdx.x;
    int v = (i < NB) ? g_bsum[i] : 0;
    int incl = block_inclusive_scan(v);
    if (i < NB) g_bsum[i] = incl - v;
}

__global__ void scan3_kernel() {   // add block offsets; init cursors; cap rowptr
    int i = blockIdx.x * blockDim.x + threadIdx.x;
    if (i < NN) {
        int val = g_rowptr[i] + g_bsum[i >> 10];
        g_rowptr[i] = val;
        g_cur[i] = val;
    }
    if (i == 0) g_rowptr[NN] = EE;
}

// fill CSR slots: src id + precomputed symmetric norm (absorbs old norm_kernel)
__global__ void fill_kernel(const int* __restrict__ ei) {
    int e = blockIdx.x * blockDim.x + threadIdx.x;
    if (e >= EE) return;
    int s = ei[e];
    int d = ei[EE + e];
    int pos = atomicAdd(&g_cur[d], 1);
    g_csr_src[pos] = s;
    g_csr_norm[pos] = g_dinv[s] * g_dinv[d];
}

// Fused: (optional bias+ReLU of previous layer) -> h @ W -> write g_t only.
template <bool FIRST>
__global__ void transform_kernel(const float* __restrict__ in,
                                 const float* __restrict__ W,
                                 const float* __restrict__ bprev) {
    __shared__ float Ws[HH * HH];
    __shared__ float Bs[HH];
    int tid = threadIdx.x;
    if (tid < HH * HH) Ws[tid] = W[tid];
    if (!FIRST && tid < HH) Bs[tid] = bprev[tid];
    __syncthreads();

    int n = blockIdx.x * blockDim.x + tid;
    if (n >= NN) return;

    float h[HH];
    if (FIRST) {
        const float4* p = (const float4*)(in + (size_t)n * HH);
#pragma unroll
        for (int q = 0; q < 4; q++) {
            float4 v = p[q];
            h[q * 4 + 0] = v.x; h[q * 4 + 1] = v.y;
            h[q * 4 + 2] = v.z; h[q * 4 + 3] = v.w;
        }
    } else {
        const float4* p = (const float4*)(g_acc + (size_t)n * HH);
#pragma unroll
        for (int q = 0; q < 4; q++) {
            float4 v = p[q];
            h[q * 4 + 0] = fmaxf(v.x + Bs[q * 4 + 0], 0.0f);
            h[q * 4 + 1] = fmaxf(v.y + Bs[q * 4 + 1], 0.0f);
            h[q * 4 + 2] = fmaxf(v.z + Bs[q * 4 + 2], 0.0f);
            h[q * 4 + 3] = fmaxf(v.w + Bs[q * 4 + 3], 0.0f);
        }
    }

    float o[HH];
#pragma unroll
    for (int j = 0; j < HH; j++) o[j] = 0.0f;
#pragma unroll
    for (int k = 0; k < HH; k++) {
#pragma unroll
        for (int j = 0; j < HH; j += 4) {
            float4 w = *(const float4*)&Ws[k * HH + j];
            o[j + 0] += h[k] * w.x;
            o[j + 1] += h[k] * w.y;
            o[j + 2] += h[k] * w.z;
            o[j + 3] += h[k] * w.w;
        }
    }

    float4* tp = (float4*)(g_t + (size_t)n * HH);
#pragma unroll
    for (int q = 0; q < 4; q++)
        tp[q] = make_float4(o[q * 4 + 0], o[q * 4 + 1], o[q * 4 + 2], o[q * 4 + 3]);
}

// Pull-mode aggregation: one warp per node. Lanes form 8 edge-slots x 4 column
// chunks; gather t[src] rows, weight by norm, shfl-reduce, add self-loop,
// write the node's 64B row once. Zero atomics.
__global__ void agg_kernel() {
    int gw = (blockIdx.x * blockDim.x + threadIdx.x) >> 5;
    if (gw >= NN) return;
    int lane = threadIdx.x & 31;
    int n = gw;
    int beg = g_rowptr[n], end = g_rowptr[n + 1];
    int c = lane & 3;      // column chunk (16B)
    int eo = lane >> 2;    // edge slot 0..7

    float4 a = make_float4(0.0f, 0.0f, 0.0f, 0.0f);
    for (int i = beg + eo; i < end; i += 8) {
        int s = g_csr_src[i];
        float w = g_csr_norm[i];
        float4 v = __ldg((const float4*)(g_t + (size_t)s * HH) + c);
        a.x += v.x * w; a.y += v.y * w; a.z += v.z * w; a.w += v.w * w;
    }
#pragma unroll
    for (int o = 16; o >= 4; o >>= 1) {
        a.x += __shfl_down_sync(0xffffffffu, a.x, o);
        a.y += __shfl_down_sync(0xffffffffu, a.y, o);
        a.z += __shfl_down_sync(0xffffffffu, a.z, o);
        a.w += __shfl_down_sync(0xffffffffu, a.w, o);
    }
    if (lane < 4) {
        float di = g_dinv[n];
        float w = di * di;                          // self-loop norm
        float4 v = *((const float4*)(g_t + (size_t)n * HH) + lane);
        a.x += v.x * w; a.y += v.y * w; a.z += v.z * w; a.w += v.w * w;
        ((float4*)(g_acc + (size_t)n * HH))[lane] = a;
    }
}

// One block per graph: binary-search sorted batch, block-reduce, head + log_softmax.
__global__ void pool_head_kernel(const int* __restrict__ batch,
                                 const float* __restrict__ b3,
                                 const float* __restrict__ Wlin,
                                 const float* __restrict__ blin,
                                 float* __restrict__ out) {
    int g = blockIdx.x;
    int tid = threadIdx.x;

    int lo = 0, hi = NN;
    while (lo < hi) { int m = (lo + hi) >> 1; if (batch[m] < g) lo = m + 1; else hi = m; }
    int beg = lo;
    lo = beg; hi = NN;
    int g1 = g + 1;
    while (lo < hi) { int m = (lo + hi) >> 1; if (batch[m] < g1) lo = m + 1; else hi = m; }
    int end = lo;

    float s[HH];
#pragma unroll
    for (int f = 0; f < HH; f++) s[f] = 0.0f;

    for (int n = beg + tid; n < end; n += blockDim.x) {
        const float4* p = (const float4*)(g_acc + (size_t)n * HH);
#pragma unroll
        for (int q = 0; q < 4; q++) {
            float4 v = p[q];
            s[q * 4 + 0] += v.x; s[q * 4 + 1] += v.y;
            s[q * 4 + 2] += v.z; s[q * 4 + 3] += v.w;
        }
    }
#pragma unroll
    for (int off = 16; off > 0; off >>= 1) {
#pragma unroll
        for (int f = 0; f < HH; f++)
            s[f] += __shfl_down_sync(0xffffffffu, s[f], off);
    }

    __shared__ float red[8][HH];
    int warp = tid >> 5, lane = tid & 31;
    if (lane == 0) {
#pragma unroll
        for (int f = 0; f < HH; f++) red[warp][f] = s[f];
    }
    __syncthreads();

    if (tid == 0) {
        float tot[HH];
        int nwarps = blockDim.x >> 5;
#pragma unroll
        for (int f = 0; f < HH; f++) {
            float t = 0.0f;
            for (int w = 0; w < nwarps; w++) t += red[w][f];
            tot[f] = t;
        }
        float cnt = (float)(end - beg);
        float inv = 1.0f / fmaxf(cnt, 1.0f);
        float pooled[HH];
#pragma unroll
        for (int f = 0; f < HH; f++) pooled[f] = (tot[f] + cnt * b3[f]) * inv;

        float logit[CC];
#pragma unroll
        for (int c = 0; c < CC; c++) {
            float a = blin[c];
#pragma unroll
            for (int f = 0; f < HH; f++) a += pooled[f] * Wlin[f * CC + c];
            logit[c] = a;
        }
        float m = logit[0];
#pragma unroll
        for (int c = 1; c < CC; c++) m = fmaxf(m, logit[c]);
        float se = 0.0f;
#pragma unroll
        for (int c = 0; c < CC; c++) se += expf(logit[c] - m);
        float lse = m + logf(se);
#pragma unroll
        for (int c = 0; c < CC; c++) out[g * CC + c] = logit[c] - lse;
    }
}

extern "C" void kernel_launch(void* const* d_in, const int* in_sizes, int n_in,
                              void* d_out, int out_size) {
    // Bind inputs by element count (robust to metadata ordering).
    const float *x = 0, *W1 = 0, *b1 = 0, *W2 = 0, *b2 = 0, *W3 = 0, *b3 = 0;
    const float *Wlin = 0, *blin = 0;
    const int *ei = 0, *batch = 0;
    int wseen = 0, bseen = 0;
    for (int i = 0; i < n_in; i++) {
        int s = in_sizes[i];
        const void* p = d_in[i];
        if (s == NN * HH)        x = (const float*)p;
        else if (s == 2 * EE)    ei = (const int*)p;
        else if (s == NN)        batch = (const int*)p;
        else if (s == HH * HH) {
            if (wseen == 0) W1 = (const float*)p;
            else if (wseen == 1) W2 = (const float*)p;
            else W3 = (const float*)p;
            wseen++;
        } else if (s == HH) {
            if (bseen == 0) b1 = (const float*)p;
            else if (bseen == 1) b2 = (const float*)p;
            else b3 = (const float*)p;
            bseen++;
        } else if (s == HH * CC) Wlin = (const float*)p;
        else if (s == CC)        blin = (const float*)p;
    }
    float* out = (float*)d_out;

    const int B = 256;
    const int gN = (NN + B - 1) / B;
    const int gE = (EE + B - 1) / B;
    const int gW = (NN * 32 + B - 1) / B;   // warp-per-node aggregation

    // CSR build
    zero_kernel<<<gN, B>>>();
    hist_kernel<<<gE, B>>>(ei);
    dinv_kernel<<<gN, B>>>();
    scan1_kernel<<<NB, 1024>>>();
    scan2_kernel<<<1, 1024>>>();
    scan3_kernel<<<gN, B>>>();
    fill_kernel<<<gE, B>>>(ei);

    // 3 GCN layers
    transform_kernel<true><<<gN, B>>>(x, W1, nullptr);
    agg_kernel<<<gW, B>>>();
    transform_kernel<false><<<gN, B>>>(nullptr, W2, b1);
    agg_kernel<<<gW, B>>>();
    transform_kernel<false><<<gN, B>>>(nullptr, W3, b2);
    agg_kernel<<<gW, B>>>();

    pool_head_kernel<<<GG, B>>>(batch, b3, Wlin, blin, out);
}